// round 1
// baseline (speedup 1.0000x reference)
#include <cuda_runtime.h>
#include <cuda_bf16.h>
#include <cstdint>

#define T_LEN 16384
#define HID   128
#define G4    512   // 4*HID gate rows

// ---------------- scratch (static device globals; no allocation) -------------
__device__ float g_gx[4u * T_LEN * G4];   // [dir: l0f,l0b,l1f,l1b][t][512]  128MB
__device__ float g_h0[T_LEN * 2 * HID];   // layer0 output [t][256]
__device__ float g_h1[T_LEN * 2 * HID];   // layer1 output [t][256]

// ---------------- f32x2 helpers (Blackwell packed FMA) -----------------------
__device__ __forceinline__ void fma2(unsigned long long& d,
                                     unsigned long long a,
                                     unsigned long long b) {
    asm("fma.rn.f32x2 %0, %1, %2, %0;" : "+l"(d) : "l"(a), "l"(b));
}
__device__ __forceinline__ float unpack_sum(unsigned long long v) {
    float lo, hi;
    asm("mov.b64 {%0,%1}, %2;" : "=f"(lo), "=f"(hi) : "l"(v));
    return lo + hi;
}

__device__ __forceinline__ float fsigmoid(float x) {
    return __fdividef(1.f, 1.f + __expf(-x));
}
__device__ __forceinline__ float ftanh(float x) {
    float a = __expf(-2.f * fabsf(x));          // in (0,1], never overflows
    float r = __fdividef(1.f - a, 1.f + a);
    return x >= 0.f ? r : -r;
}

// ---------------- kernel 1: layer-0 input projection (IN=1) ------------------
__global__ void k_gx0(const float* __restrict__ x,
                      const float* __restrict__ wf, const float* __restrict__ bfi,
                      const float* __restrict__ bfh,
                      const float* __restrict__ wb, const float* __restrict__ bbi,
                      const float* __restrict__ bbh,
                      float* __restrict__ gxf, float* __restrict__ gxb) {
    unsigned idx = blockIdx.x * 256u + threadIdx.x;
    if (idx >= (unsigned)T_LEN * G4) return;
    unsigned t = idx >> 9, r = idx & 511u;
    float xv = x[t];
    gxf[idx] = xv * wf[r] + bfi[r] + bfh[r];
    gxb[idx] = xv * wb[r] + bbi[r] + bbh[r];
}

// ---------------- kernel 2: the recurrent scan (2 CTAs: fwd, bwd) ------------
// smem: sw[24][512][4] fp32 weights for k=32..127 (192KB) + h (128) + gates (512)
#define SW_FLOATS (24 * 512 * 4)
#define SMEM_LSTM_BYTES ((SW_FLOATS + 128 + 512) * 4)

__global__ void __launch_bounds__(512, 1)
k_lstm(const float* __restrict__ gx_f, const float* __restrict__ gx_b,
       const float* __restrict__ whh_f, const float* __restrict__ whh_b,
       float* __restrict__ hcat) {
    const int dir = blockIdx.x;                     // 0 fwd, 1 bwd
    const float* gx  = dir ? gx_b  : gx_f;
    const float* whh = dir ? whh_b : whh_f;

    extern __shared__ float sm[];
    float* sw     = sm;                   // [24*512*4]
    float* h_s    = sm + SW_FLOATS;       // [128], 16B aligned
    float* gate_s = h_s + 128;            // [512]

    const int r = threadIdx.x;            // gate row 0..511

    // stage weights: k=0..31 into registers (as packed f32x2 pairs),
    //                k=32..127 into smem in [kgroup][row][4] layout
    const float4* wrow = (const float4*)(whh + (size_t)r * HID);
    ulonglong2 wr[8];
#pragma unroll
    for (int i = 0; i < 8; i++)
        wr[i] = ((const ulonglong2*)wrow)[i];       // w[4i..4i+3]
#pragma unroll
    for (int g = 0; g < 24; g++)
        ((float4*)sw)[g * 512 + r] = wrow[8 + g];   // w[32+4g .. 32+4g+3]
    if (r < HID) h_s[r] = 0.f;
    __syncthreads();

    float c = 0.f;
    const int col = dir * HID + (r & (HID - 1));

    int t_first = dir ? (T_LEN - 1) : 0;
    float gx_next = gx[(size_t)t_first * G4 + r];

    for (int s = 0; s < T_LEN; ++s) {
        const int t = dir ? (T_LEN - 1 - s) : s;
        const float gxv = gx_next;
        int t2 = dir ? (t - 1) : (t + 1);
        if (s == T_LEN - 1) t2 = t;
        gx_next = gx[(size_t)t2 * G4 + r];          // prefetch next step

        unsigned long long a0 = 0ull, a1 = 0ull;    // bit pattern of (0.f,0.f)
        const ulonglong2* h2  = (const ulonglong2*)h_s;   // h[4i..4i+3] per elt
#pragma unroll
        for (int i = 0; i < 8; i++) {               // k = 0..31 (register wts)
            ulonglong2 hv = h2[i];
            fma2(a0, wr[i].x, hv.x);
            fma2(a1, wr[i].y, hv.y);
        }
        const ulonglong2* sw2 = (const ulonglong2*)sw;
#pragma unroll
        for (int g = 0; g < 24; g++) {              // k = 32..127 (smem wts)
            ulonglong2 wv = sw2[g * 512 + r];       // lane-consecutive: no conflict
            ulonglong2 hv = h2[8 + g];              // broadcast
            fma2(a0, wv.x, hv.x);
            fma2(a1, wv.y, hv.y);
        }
        gate_s[r] = gxv + (unpack_sum(a0) + unpack_sum(a1));
        __syncthreads();

        if (r < HID) {
            float iv = fsigmoid(gate_s[r]);
            float fv = fsigmoid(gate_s[HID + r]);
            float gv = ftanh   (gate_s[2 * HID + r]);
            float ov = fsigmoid(gate_s[3 * HID + r]);
            c = fv * c + iv * gv;
            float h = ov * ftanh(c);
            h_s[r] = h;
            hcat[(size_t)t * (2 * HID) + col] = h;  // fire-and-forget
        }
        __syncthreads();
    }
}

// ---------------- kernel 3: layer-1 input projection GEMM --------------------
// gx1[d][t][r] = sum_k W[d][r][k] * h0[t][k] + b_i[r] + b_h[r]
__global__ void __launch_bounds__(512)
k_gx1(const float* __restrict__ h0,
      const float* __restrict__ Wf, const float* __restrict__ bfi,
      const float* __restrict__ bfh,
      const float* __restrict__ Wb, const float* __restrict__ bbi,
      const float* __restrict__ bbh,
      float* __restrict__ gxf, float* __restrict__ gxb) {
    const int dir = blockIdx.y;
    const float* W  = dir ? Wb  : Wf;
    const float* bi = dir ? bbi : bfi;
    const float* bh = dir ? bbh : bfh;
    float* gx       = dir ? gxb : gxf;

    __shared__ float hs[32 * 256];                  // 32 timesteps of h0
    const int t0 = blockIdx.x * 32;
    const int r  = threadIdx.x;

    for (int idx = r; idx < 32 * 256; idx += 512)
        hs[idx] = h0[(size_t)t0 * 256 + idx];
    __syncthreads();

    float acc[32];
    const float bias = bi[r] + bh[r];
#pragma unroll
    for (int tt = 0; tt < 32; tt++) acc[tt] = bias;

    const float4* wrow = (const float4*)(W + (size_t)r * 256);
    for (int k4 = 0; k4 < 64; k4++) {
        float4 w4 = wrow[k4];
#pragma unroll
        for (int tt = 0; tt < 32; tt++) {
            float4 hv = *(const float4*)(hs + tt * 256 + k4 * 4);  // broadcast
            acc[tt] += w4.x * hv.x + w4.y * hv.y + w4.z * hv.z + w4.w * hv.w;
        }
    }
#pragma unroll
    for (int tt = 0; tt < 32; tt++)
        gx[(size_t)(t0 + tt) * G4 + r] = acc[tt];
}

// ---------------- kernel 4: FC head ------------------------------------------
// y[t] = fc2 @ leaky(fc1 @ h1[t] + b1, 0.01) + b2
__global__ void __launch_bounds__(128)
k_head(const float* __restrict__ h1,
       const float* __restrict__ fc1w, const float* __restrict__ fc1b,
       const float* __restrict__ fc2w, const float* __restrict__ fc2b,
       float* __restrict__ out) {
    __shared__ float hs[8 * 256];
    __shared__ float z[8 * 128];
    const int t0 = blockIdx.x * 8;
    const int j  = threadIdx.x;

    for (int idx = j; idx < 8 * 256; idx += 128)
        hs[idx] = h1[(size_t)t0 * 256 + idx];
    __syncthreads();

    float acc[8];
    const float b = fc1b[j];
#pragma unroll
    for (int tt = 0; tt < 8; tt++) acc[tt] = b;

    const float4* wrow = (const float4*)(fc1w + (size_t)j * 256);
    for (int k4 = 0; k4 < 64; k4++) {
        float4 w4 = wrow[k4];
#pragma unroll
        for (int tt = 0; tt < 8; tt++) {
            float4 hv = *(const float4*)(hs + tt * 256 + k4 * 4);
            acc[tt] += w4.x * hv.x + w4.y * hv.y + w4.z * hv.z + w4.w * hv.w;
        }
    }
#pragma unroll
    for (int tt = 0; tt < 8; tt++) {
        float a = acc[tt];
        z[tt * 128 + j] = a > 0.f ? a : 0.01f * a;
    }
    __syncthreads();

    const int wid  = j >> 5;
    const int lane = j & 31;
#pragma unroll
    for (int q = 0; q < 2; q++) {
        int tt = wid * 2 + q;
        const float* zz = z + tt * 128;
        float s = fc2w[lane]      * zz[lane]
                + fc2w[lane + 32] * zz[lane + 32]
                + fc2w[lane + 64] * zz[lane + 64]
                + fc2w[lane + 96] * zz[lane + 96];
#pragma unroll
        for (int off = 16; off > 0; off >>= 1)
            s += __shfl_down_sync(0xFFFFFFFFu, s, off);
        if (lane == 0)
            out[t0 + tt] = s + fc2b[0];
    }
}

// ---------------- launcher ---------------------------------------------------
extern "C" void kernel_launch(void* const* d_in, const int* in_sizes, int n_in,
                              void* d_out, int out_size) {
    const float* x        = (const float*)d_in[0];
    const float* w_ih_l0  = (const float*)d_in[1];
    const float* w_hh_l0  = (const float*)d_in[2];
    const float* b_ih_l0  = (const float*)d_in[3];
    const float* b_hh_l0  = (const float*)d_in[4];
    const float* w_ih_l0r = (const float*)d_in[5];
    const float* w_hh_l0r = (const float*)d_in[6];
    const float* b_ih_l0r = (const float*)d_in[7];
    const float* b_hh_l0r = (const float*)d_in[8];
    const float* w_ih_l1  = (const float*)d_in[9];
    const float* w_hh_l1  = (const float*)d_in[10];
    const float* b_ih_l1  = (const float*)d_in[11];
    const float* b_hh_l1  = (const float*)d_in[12];
    const float* w_ih_l1r = (const float*)d_in[13];
    const float* w_hh_l1r = (const float*)d_in[14];
    const float* b_ih_l1r = (const float*)d_in[15];
    const float* b_hh_l1r = (const float*)d_in[16];
    const float* fc1_w    = (const float*)d_in[17];
    const float* fc1_b    = (const float*)d_in[18];
    const float* fc2_w    = (const float*)d_in[19];
    const float* fc2_b    = (const float*)d_in[20];
    float* out = (float*)d_out;

    float *gx_base, *h0, *h1;
    cudaGetSymbolAddress((void**)&gx_base, g_gx);
    cudaGetSymbolAddress((void**)&h0, g_h0);
    cudaGetSymbolAddress((void**)&h1, g_h1);
    float* gx0f = gx_base;
    float* gx0b = gx_base + (size_t)1 * T_LEN * G4;
    float* gx1f = gx_base + (size_t)2 * T_LEN * G4;
    float* gx1b = gx_base + (size_t)3 * T_LEN * G4;

    cudaFuncSetAttribute(k_lstm, cudaFuncAttributeMaxDynamicSharedMemorySize,
                         SMEM_LSTM_BYTES);

    k_gx0<<<(T_LEN * G4 + 255) / 256, 256>>>(x, w_ih_l0, b_ih_l0, b_hh_l0,
                                             w_ih_l0r, b_ih_l0r, b_hh_l0r,
                                             gx0f, gx0b);
    k_lstm<<<2, 512, SMEM_LSTM_BYTES>>>(gx0f, gx0b, w_hh_l0, w_hh_l0r, h0);
    k_gx1<<<dim3(T_LEN / 32, 2), 512>>>(h0, w_ih_l1, b_ih_l1, b_hh_l1,
                                        w_ih_l1r, b_ih_l1r, b_hh_l1r,
                                        gx1f, gx1b);
    k_lstm<<<2, 512, SMEM_LSTM_BYTES>>>(gx1f, gx1b, w_hh_l1, w_hh_l1r, h1);
    k_head<<<T_LEN / 8, 128>>>(h1, fc1_w, fc1_b, fc2_w, fc2_b, out);
}

// round 2
// speedup vs baseline: 1.4910x; 1.4910x over previous
#include <cuda_runtime.h>
#include <cuda_bf16.h>
#include <cstdint>

#define T_LEN 16384
#define HID   128
#define G4    512   // 4*HID gate rows

// ---------------- scratch (static device globals; no allocation) -------------
__device__ float g_gx[4u * T_LEN * G4];   // [l0f,l0b,l1f,l1b][t][512]
__device__ float g_h0[T_LEN * 2 * HID];   // layer0 output [t][256]
__device__ float g_h1[T_LEN * 2 * HID];   // layer1 output [t][256]

// ---------------- f32x2 helpers (Blackwell packed FMA) -----------------------
__device__ __forceinline__ void fma2(unsigned long long& d,
                                     unsigned long long a,
                                     unsigned long long b) {
    asm("fma.rn.f32x2 %0, %1, %2, %0;" : "+l"(d) : "l"(a), "l"(b));
}
__device__ __forceinline__ float unpack_sum(unsigned long long v) {
    float lo, hi;
    asm("mov.b64 {%0,%1}, %2;" : "=f"(lo), "=f"(hi) : "l"(v));
    return lo + hi;
}
__device__ __forceinline__ uint32_t smem_u32(const void* p) {
    uint32_t a;
    asm("{ .reg .u64 t; cvta.to.shared.u64 t, %1; cvt.u32.u64 %0, t; }"
        : "=r"(a) : "l"(p));
    return a;
}

__device__ __forceinline__ float fsigmoid(float x) {
    return __fdividef(1.f, 1.f + __expf(-x));
}
__device__ __forceinline__ float ftanh(float x) {
    float a = __expf(-2.f * fabsf(x));
    float r = __fdividef(1.f - a, 1.f + a);
    return x >= 0.f ? r : -r;
}

// ---------------- kernel 1: layer-0 input projection (IN=1) ------------------
__global__ void k_gx0(const float* __restrict__ x,
                      const float* __restrict__ wf, const float* __restrict__ bfi,
                      const float* __restrict__ bfh,
                      const float* __restrict__ wb, const float* __restrict__ bbi,
                      const float* __restrict__ bbh,
                      float* __restrict__ gxf, float* __restrict__ gxb) {
    unsigned idx = blockIdx.x * 256u + threadIdx.x;
    if (idx >= (unsigned)T_LEN * G4) return;
    unsigned t = idx >> 9, r = idx & 511u;
    float xv = x[t];
    gxf[idx] = xv * wf[r] + bfi[r] + bfh[r];
    gxb[idx] = xv * wb[r] + bbi[r] + bbh[r];
}

// ---------------- kernel 2: recurrent scan, 2-CTA cluster per direction ------
// Grid = 4 CTAs, cluster size 2. Cluster 0 = fwd, cluster 1 = bwd.
// CTA rank r owns hidden units [64r, 64r+64): its 256 gate rows (i,f,g,o of
// those units). ALL 32K weight floats live in registers (64/thread).
// h is exchanged per step via DSMEM (256 B) + mbarrier, double-buffered.
//
// h buffer layout (per buffer, 144 floats): units 0..63 at [0..63],
// units 64..127 at [68..131] (4-float pad => kh0/kh1 broadcast loads hit
// disjoint bank groups). Buffers at +0 and +144 floats.
__global__ void __launch_bounds__(512, 1) __cluster_dims__(2, 1, 1)
k_lstm2(const float* __restrict__ gx_f, const float* __restrict__ gx_b,
        const float* __restrict__ whh_f, const float* __restrict__ whh_b,
        float* __restrict__ hcat) {
    __shared__ alignas(16) float hbuf[2 * 144];
    __shared__ float gate_s[256];
    __shared__ alignas(8) unsigned long long mbar;

    const int dir = blockIdx.x >> 1;
    uint32_t rank;
    asm("mov.u32 %0, %%cluster_ctarank;" : "=r"(rank));
    const float* gx  = dir ? gx_b  : gx_f;
    const float* whh = dir ? whh_b : whh_f;

    const int tid  = threadIdx.x;
    const int lr   = tid >> 1;          // local gate row 0..255
    const int kh   = tid & 1;           // k-half 0/1
    const int gate = lr >> 6;           // 0=i 1=f 2=g 3=o
    const int u    = lr & 63;           // unit within this CTA's 64
    const int grow = gate * HID + (int)rank * 64 + u;   // global gate row

    // ---- stage this thread's 64 weights into registers ----
    ulonglong2 wr[16];
    const ulonglong2* wsrc =
        (const ulonglong2*)(whh + (size_t)grow * HID + kh * 64);
#pragma unroll
    for (int i = 0; i < 16; i++) wr[i] = wsrc[i];

    // ---- init: h(-1)=0 in both buffers; mbarrier count=64 ----
    if (tid < 288) hbuf[tid] = 0.f;
    const uint32_t mbar_a = smem_u32(&mbar);
    const uint32_t hbuf_a = smem_u32(hbuf);
    if (tid == 0)
        asm volatile("mbarrier.init.shared.b64 [%0], %1;"
                     :: "r"(mbar_a), "r"(64u) : "memory");
    __syncthreads();

    // peer (other CTA in cluster) smem addresses via mapa
    const uint32_t prank = rank ^ 1u;
    uint32_t peer_hbuf, peer_mbar;
    asm("mapa.shared::cluster.u32 %0, %1, %2;"
        : "=r"(peer_hbuf) : "r"(hbuf_a), "r"(prank));
    asm("mapa.shared::cluster.u32 %0, %1, %2;"
        : "=r"(peer_mbar) : "r"(mbar_a), "r"(prank));

    // both CTAs' inits must be visible before any remote traffic
    asm volatile("barrier.cluster.arrive.aligned;" ::: "memory");
    asm volatile("barrier.cluster.wait.aligned;" ::: "memory");

    float c = 0.f;                                      // cell state (tid<64)
    const int t_first = dir ? (T_LEN - 1) : 0;
    float gx_next = gx[(size_t)t_first * G4 + grow];

    for (int s = 0; s < T_LEN; ++s) {
        const int t = dir ? (T_LEN - 1 - s) : s;
        const float gxv = gx_next;
        int t2 = dir ? (t - 1) : (t + 1);
        if (s == T_LEN - 1) t2 = t;
        gx_next = gx[(size_t)t2 * G4 + grow];           // prefetch next step

        // ---- matvec over this thread's k-half; reads h(s-1) buffer ----
        const int rd = (s & 1) ^ 1;                     // h(s-1) lives here
        const ulonglong2* hb =
            (const ulonglong2*)(hbuf + rd * 144 + kh * 68);
        unsigned long long a0 = 0ull, a1 = 0ull;
#pragma unroll
        for (int i = 0; i < 16; i++) {
            ulonglong2 hv = hb[i];                      // broadcast load
            fma2(a0, wr[i].x, hv.x);
            fma2(a1, wr[i].y, hv.y);
        }
        float psum = unpack_sum(a0) + unpack_sum(a1);
        psum += __shfl_xor_sync(0xFFFFFFFFu, psum, 1);  // combine k-halves
        if (kh == 0) gate_s[lr] = gxv + psum;
        __syncthreads();                                 // gates ready; h reads done

        // ---- elementwise LSTM cell: thread j<64 owns unit (rank*64+j) ----
        if (tid < 64) {
            float iv = fsigmoid(gate_s[tid]);
            float fv = fsigmoid(gate_s[64 + tid]);
            float gv = ftanh   (gate_s[128 + tid]);
            float ov = fsigmoid(gate_s[192 + tid]);
            c = fv * c + iv * gv;
            float h = ov * ftanh(c);

            const int woff = (s & 1) * 144 + (int)rank * 68 + tid;
            hbuf[woff] = h;                              // local copy
            asm volatile("st.shared::cluster.f32 [%0], %1;"
                         :: "r"(peer_hbuf + (uint32_t)(woff * 4)), "f"(h)
                         : "memory");
            asm volatile(
                "mbarrier.arrive.release.cluster.shared::cluster.b64 _, [%0];"
                :: "r"(peer_mbar) : "memory");
            hcat[(size_t)t * (2 * HID) + dir * HID + (int)rank * 64 + tid] = h;
        }
        __syncthreads();                                 // local h visible

        // ---- wait for peer's 64 h values (phase parity = s&1) ----
        {
            const unsigned par = (unsigned)(s & 1);
            unsigned done;
            asm volatile(
                "{\n\t.reg .pred p;\n\t"
                "mbarrier.try_wait.parity.acquire.cluster.shared::cta.b64 p, [%1], %2, 0x989680;\n\t"
                "selp.b32 %0, 1, 0, p;\n\t}"
                : "=r"(done) : "r"(mbar_a), "r"(par) : "memory");
            while (!done) {
                asm volatile(
                    "{\n\t.reg .pred p;\n\t"
                    "mbarrier.try_wait.parity.acquire.cluster.shared::cta.b64 p, [%1], %2, 0x989680;\n\t"
                    "selp.b32 %0, 1, 0, p;\n\t}"
                    : "=r"(done) : "r"(mbar_a), "r"(par) : "memory");
            }
        }
    }

    // no CTA may exit while peer remote stores/arrives could be in flight
    asm volatile("barrier.cluster.arrive.aligned;" ::: "memory");
    asm volatile("barrier.cluster.wait.aligned;" ::: "memory");
}

// ---------------- kernel 3: layer-1 input projection GEMM --------------------
__global__ void __launch_bounds__(512)
k_gx1(const float* __restrict__ h0,
      const float* __restrict__ Wf, const float* __restrict__ bfi,
      const float* __restrict__ bfh,
      const float* __restrict__ Wb, const float* __restrict__ bbi,
      const float* __restrict__ bbh,
      float* __restrict__ gxf, float* __restrict__ gxb) {
    const int dir = blockIdx.y;
    const float* W  = dir ? Wb  : Wf;
    const float* bi = dir ? bbi : bfi;
    const float* bh = dir ? bbh : bfh;
    float* gx       = dir ? gxb : gxf;

    __shared__ float hs[32 * 256];
    const int t0 = blockIdx.x * 32;
    const int r  = threadIdx.x;

    for (int idx = r; idx < 32 * 256; idx += 512)
        hs[idx] = h0[(size_t)t0 * 256 + idx];
    __syncthreads();

    float acc[32];
    const float bias = bi[r] + bh[r];
#pragma unroll
    for (int tt = 0; tt < 32; tt++) acc[tt] = bias;

    const float4* wrow = (const float4*)(W + (size_t)r * 256);
    for (int k4 = 0; k4 < 64; k4++) {
        float4 w4 = wrow[k4];
#pragma unroll
        for (int tt = 0; tt < 32; tt++) {
            float4 hv = *(const float4*)(hs + tt * 256 + k4 * 4);
            acc[tt] += w4.x * hv.x + w4.y * hv.y + w4.z * hv.z + w4.w * hv.w;
        }
    }
#pragma unroll
    for (int tt = 0; tt < 32; tt++)
        gx[(size_t)(t0 + tt) * G4 + r] = acc[tt];
}

// ---------------- kernel 4: FC head ------------------------------------------
__global__ void __launch_bounds__(128)
k_head(const float* __restrict__ h1,
       const float* __restrict__ fc1w, const float* __restrict__ fc1b,
       const float* __restrict__ fc2w, const float* __restrict__ fc2b,
       float* __restrict__ out) {
    __shared__ float hs[8 * 256];
    __shared__ float z[8 * 128];
    const int t0 = blockIdx.x * 8;
    const int j  = threadIdx.x;

    for (int idx = j; idx < 8 * 256; idx += 128)
        hs[idx] = h1[(size_t)t0 * 256 + idx];
    __syncthreads();

    float acc[8];
    const float b = fc1b[j];
#pragma unroll
    for (int tt = 0; tt < 8; tt++) acc[tt] = b;

    const float4* wrow = (const float4*)(fc1w + (size_t)j * 256);
    for (int k4 = 0; k4 < 64; k4++) {
        float4 w4 = wrow[k4];
#pragma unroll
        for (int tt = 0; tt < 8; tt++) {
            float4 hv = *(const float4*)(hs + tt * 256 + k4 * 4);
            acc[tt] += w4.x * hv.x + w4.y * hv.y + w4.z * hv.z + w4.w * hv.w;
        }
    }
#pragma unroll
    for (int tt = 0; tt < 8; tt++) {
        float a = acc[tt];
        z[tt * 128 + j] = a > 0.f ? a : 0.01f * a;
    }
    __syncthreads();

    const int wid  = j >> 5;
    const int lane = j & 31;
#pragma unroll
    for (int q = 0; q < 2; q++) {
        int tt = wid * 2 + q;
        const float* zz = z + tt * 128;
        float s = fc2w[lane]      * zz[lane]
                + fc2w[lane + 32] * zz[lane + 32]
                + fc2w[lane + 64] * zz[lane + 64]
                + fc2w[lane + 96] * zz[lane + 96];
#pragma unroll
        for (int off = 16; off > 0; off >>= 1)
            s += __shfl_down_sync(0xFFFFFFFFu, s, off);
        if (lane == 0)
            out[t0 + tt] = s + fc2b[0];
    }
}

// ---------------- launcher ---------------------------------------------------
extern "C" void kernel_launch(void* const* d_in, const int* in_sizes, int n_in,
                              void* d_out, int out_size) {
    const float* x        = (const float*)d_in[0];
    const float* w_ih_l0  = (const float*)d_in[1];
    const float* w_hh_l0  = (const float*)d_in[2];
    const float* b_ih_l0  = (const float*)d_in[3];
    const float* b_hh_l0  = (const float*)d_in[4];
    const float* w_ih_l0r = (const float*)d_in[5];
    const float* w_hh_l0r = (const float*)d_in[6];
    const float* b_ih_l0r = (const float*)d_in[7];
    const float* b_hh_l0r = (const float*)d_in[8];
    const float* w_ih_l1  = (const float*)d_in[9];
    const float* w_hh_l1  = (const float*)d_in[10];
    const float* b_ih_l1  = (const float*)d_in[11];
    const float* b_hh_l1  = (const float*)d_in[12];
    const float* w_ih_l1r = (const float*)d_in[13];
    const float* w_hh_l1r = (const float*)d_in[14];
    const float* b_ih_l1r = (const float*)d_in[15];
    const float* b_hh_l1r = (const float*)d_in[16];
    const float* fc1_w    = (const float*)d_in[17];
    const float* fc1_b    = (const float*)d_in[18];
    const float* fc2_w    = (const float*)d_in[19];
    const float* fc2_b    = (const float*)d_in[20];
    float* out = (float*)d_out;

    float *gx_base, *h0, *h1;
    cudaGetSymbolAddress((void**)&gx_base, g_gx);
    cudaGetSymbolAddress((void**)&h0, g_h0);
    cudaGetSymbolAddress((void**)&h1, g_h1);
    float* gx0f = gx_base;
    float* gx0b = gx_base + (size_t)1 * T_LEN * G4;
    float* gx1f = gx_base + (size_t)2 * T_LEN * G4;
    float* gx1b = gx_base + (size_t)3 * T_LEN * G4;

    k_gx0<<<(T_LEN * G4 + 255) / 256, 256>>>(x, w_ih_l0, b_ih_l0, b_hh_l0,
                                             w_ih_l0r, b_ih_l0r, b_hh_l0r,
                                             gx0f, gx0b);
    k_lstm2<<<4, 512>>>(gx0f, gx0b, w_hh_l0, w_hh_l0r, h0);
    k_gx1<<<dim3(T_LEN / 32, 2), 512>>>(h0, w_ih_l1, b_ih_l1, b_hh_l1,
                                        w_ih_l1r, b_ih_l1r, b_hh_l1r,
                                        gx1f, gx1b);
    k_lstm2<<<4, 512>>>(gx1f, gx1b, w_hh_l1, w_hh_l1r, h1);
    k_head<<<T_LEN / 8, 128>>>(h1, fc1_w, fc1_b, fc2_w, fc2_b, out);
}

// round 3
// speedup vs baseline: 1.6251x; 1.0899x over previous
#include <cuda_runtime.h>
#include <cuda_bf16.h>
#include <cstdint>

#define T_LEN 16384
#define HID   128
#define G4    512   // 4*HID gate rows

// ---------------- scratch (static device globals; no allocation) -------------
// gx layout: [t][unit 0..127][gate i,f,g,o]  (float4 per unit)
__device__ float g_gx[4u * T_LEN * G4];   // [l0f,l0b,l1f,l1b]
__device__ float g_h0[T_LEN * 2 * HID];   // layer0 output [t][256]
__device__ float g_h1[T_LEN * 2 * HID];   // layer1 output [t][256]

// ---------------- f32x2 helpers ----------------------------------------------
__device__ __forceinline__ void fma2(unsigned long long& d,
                                     unsigned long long a,
                                     unsigned long long b) {
    asm("fma.rn.f32x2 %0, %1, %2, %0;" : "+l"(d) : "l"(a), "l"(b));
}
__device__ __forceinline__ float unpack_sum(unsigned long long v) {
    float lo, hi;
    asm("mov.b64 {%0,%1}, %2;" : "=f"(lo), "=f"(hi) : "l"(v));
    return lo + hi;
}
__device__ __forceinline__ uint32_t smem_u32(const void* p) {
    uint32_t a;
    asm("{ .reg .u64 t; cvta.to.shared.u64 t, %1; cvt.u32.u64 %0, t; }"
        : "=r"(a) : "l"(p));
    return a;
}
__device__ __forceinline__ float fsigmoid(float x) {
    return __fdividef(1.f, 1.f + __expf(-x));
}
__device__ __forceinline__ float ftanh(float x) {
    float a = __expf(-2.f * fabsf(x));
    float r = __fdividef(1.f - a, 1.f + a);
    return x >= 0.f ? r : -r;
}

// ---------------- kernel 1: layer-0 input projection (IN=1) ------------------
__global__ void k_gx0(const float* __restrict__ x,
                      const float* __restrict__ wf, const float* __restrict__ bfi,
                      const float* __restrict__ bfh,
                      const float* __restrict__ wb, const float* __restrict__ bbi,
                      const float* __restrict__ bbh,
                      float* __restrict__ gxf, float* __restrict__ gxb) {
    unsigned idx = blockIdx.x * 256u + threadIdx.x;
    if (idx >= (unsigned)T_LEN * G4) return;
    unsigned t = idx >> 9, r = idx & 511u;             // r = gate*128 + unit
    unsigned dst = t * G4 + (r & 127u) * 4u + (r >> 7);
    float xv = x[t];
    gxf[dst] = xv * wf[r] + bfi[r] + bfh[r];
    gxb[dst] = xv * wb[r] + bbi[r] + bbh[r];
}

// ---------------- kernel 2: recurrent scan, 2-CTA cluster per direction ------
// Grid = 4 CTAs, cluster size 2; cluster 0 = fwd, 1 = bwd.
// CTA rank owns hidden units [64*rank, 64*rank+64).
// Warp w (0..15) owns units rank*64 + 4w .. +4w+3.
// Lane l: unit u = w*4 + (l&3), k-eighth e = l>>2 (8 floats per half per gate).
// All weights in registers (64 floats/thread). Gate reduce = shfl butterfly.
// No __syncthreads in the loop; ordering via two mbarriers.
__global__ void __launch_bounds__(512, 1) __cluster_dims__(2, 1, 1)
k_lstm2(const float* __restrict__ gx_f, const float* __restrict__ gx_b,
        const float* __restrict__ whh_f, const float* __restrict__ whh_b,
        float* __restrict__ hcat) {
    __shared__ alignas(16) float hbuf[2 * 136];   // [buf][half*68 + unit]
    __shared__ alignas(8) unsigned long long bar_loc;
    __shared__ alignas(8) unsigned long long bar_rem;

    const int dir = blockIdx.x >> 1;
    uint32_t rank;
    asm("mov.u32 %0, %%cluster_ctarank;" : "=r"(rank));
    const float* gx  = dir ? gx_b  : gx_f;
    const float* whh = dir ? whh_b : whh_f;

    const int tid  = threadIdx.x;
    const int w    = tid >> 5;
    const int l    = tid & 31;
    const int u    = (w << 2) | (l & 3);        // local unit 0..63
    const int e    = l >> 2;                    // k-eighth 0..7
    const bool wr_lane = (e == 0);
    const int gu   = (int)rank * 64 + u;        // global unit

    const int kA = (int)rank * 64 + e * 8;      // local-half k slice
    const int kB = ((int)rank ^ 1) * 64 + e * 8;// peer-half k slice

    // ---- stage weights: 4 gates x 2 phases x 8 floats ----
    ulonglong2 wv[4][2][2];
#pragma unroll
    for (int g = 0; g < 4; g++) {
        const float* row = whh + (size_t)(g * HID + gu) * HID;
        const ulonglong2* pA = (const ulonglong2*)(row + kA);
        const ulonglong2* pB = (const ulonglong2*)(row + kB);
        wv[g][0][0] = pA[0]; wv[g][0][1] = pA[1];
        wv[g][1][0] = pB[0]; wv[g][1][1] = pB[1];
    }

    // ---- init ----
    if (tid < 272) hbuf[tid] = 0.f;
    const uint32_t bl_a = smem_u32(&bar_loc);
    const uint32_t br_a = smem_u32(&bar_rem);
    const uint32_t hb_a = smem_u32(hbuf);
    if (tid == 0) {
        asm volatile("mbarrier.init.shared.b64 [%0], %1;"
                     :: "r"(bl_a), "r"(64u) : "memory");
        asm volatile("mbarrier.init.shared.b64 [%0], %1;"
                     :: "r"(br_a), "r"(64u) : "memory");
    }
    __syncthreads();

    const uint32_t prank = rank ^ 1u;
    uint32_t peer_hbuf, peer_brem;
    asm("mapa.shared::cluster.u32 %0, %1, %2;"
        : "=r"(peer_hbuf) : "r"(hb_a), "r"(prank));
    asm("mapa.shared::cluster.u32 %0, %1, %2;"
        : "=r"(peer_brem) : "r"(br_a), "r"(prank));

    asm volatile("barrier.cluster.arrive.aligned;" ::: "memory");
    asm volatile("barrier.cluster.wait.aligned;" ::: "memory");

    float c = 0.f;
    const int t_first = dir ? (T_LEN - 1) : 0;
    float4 gx_next = make_float4(0.f, 0.f, 0.f, 0.f);
    if (wr_lane)
        gx_next = ((const float4*)gx)[(size_t)t_first * HID + gu];

    for (int s = 0; s < T_LEN; ++s) {
        const int t = dir ? (T_LEN - 1 - s) : s;
        const float4 gxv = gx_next;
        const int rd = (s & 1) ^ 1;                   // buffer holding h(s-1)
        const unsigned par = (unsigned)((s - 1) & 1); // parity of h(s-1) flip

        if (s) {
            // wait for LOCAL h(s-1)
            unsigned done;
            do {
                asm volatile(
                    "{\n\t.reg .pred p;\n\t"
                    "mbarrier.try_wait.parity.acquire.cta.shared::cta.b64 p, [%1], %2, 0x989680;\n\t"
                    "selp.b32 %0, 1, 0, p;\n\t}"
                    : "=r"(done) : "r"(bl_a), "r"(par) : "memory");
            } while (!done);
        }
        if (wr_lane) {                                 // prefetch next gx
            int t2 = dir ? (t - 1) : (t + 1);
            if (s == T_LEN - 1) t2 = t;
            gx_next = ((const float4*)gx)[(size_t)t2 * HID + gu];
        }

        unsigned long long a0 = 0ull, a1 = 0ull, a2 = 0ull, a3 = 0ull;
        // ---- phase A: local-half k (h written by this CTA) ----
        {
            const ulonglong2* hA =
                (const ulonglong2*)(hbuf + rd * 136 + (int)rank * 68 + e * 8);
            ulonglong2 h0v = hA[0], h1v = hA[1];
            fma2(a0, wv[0][0][0].x, h0v.x); fma2(a0, wv[0][0][0].y, h0v.y);
            fma2(a1, wv[1][0][0].x, h0v.x); fma2(a1, wv[1][0][0].y, h0v.y);
            fma2(a2, wv[2][0][0].x, h0v.x); fma2(a2, wv[2][0][0].y, h0v.y);
            fma2(a3, wv[3][0][0].x, h0v.x); fma2(a3, wv[3][0][0].y, h0v.y);
            fma2(a0, wv[0][0][1].x, h1v.x); fma2(a0, wv[0][0][1].y, h1v.y);
            fma2(a1, wv[1][0][1].x, h1v.x); fma2(a1, wv[1][0][1].y, h1v.y);
            fma2(a2, wv[2][0][1].x, h1v.x); fma2(a2, wv[2][0][1].y, h1v.y);
            fma2(a3, wv[3][0][1].x, h1v.x); fma2(a3, wv[3][0][1].y, h1v.y);
        }
        // ---- wait for PEER h(s-1) (latency overlapped phase A) ----
        if (s) {
            unsigned done;
            do {
                asm volatile(
                    "{\n\t.reg .pred p;\n\t"
                    "mbarrier.try_wait.parity.acquire.cluster.shared::cta.b64 p, [%1], %2, 0x989680;\n\t"
                    "selp.b32 %0, 1, 0, p;\n\t}"
                    : "=r"(done) : "r"(br_a), "r"(par) : "memory");
            } while (!done);
        }
        // ---- phase B: peer-half k ----
        {
            const ulonglong2* hB =
                (const ulonglong2*)(hbuf + rd * 136 + ((int)prank) * 68 + e * 8);
            ulonglong2 h0v = hB[0], h1v = hB[1];
            fma2(a0, wv[0][1][0].x, h0v.x); fma2(a0, wv[0][1][0].y, h0v.y);
            fma2(a1, wv[1][1][0].x, h0v.x); fma2(a1, wv[1][1][0].y, h0v.y);
            fma2(a2, wv[2][1][0].x, h0v.x); fma2(a2, wv[2][1][0].y, h0v.y);
            fma2(a3, wv[3][1][0].x, h0v.x); fma2(a3, wv[3][1][0].y, h0v.y);
            fma2(a0, wv[0][1][1].x, h1v.x); fma2(a0, wv[0][1][1].y, h1v.y);
            fma2(a1, wv[1][1][1].x, h1v.x); fma2(a1, wv[1][1][1].y, h1v.y);
            fma2(a2, wv[2][1][1].x, h1v.x); fma2(a2, wv[2][1][1].y, h1v.y);
            fma2(a3, wv[3][1][1].x, h1v.x); fma2(a3, wv[3][1][1].y, h1v.y);
        }

        // ---- butterfly reduce over the 8 k-eighth lanes ----
        float gi = unpack_sum(a0);
        float gf = unpack_sum(a1);
        float gg = unpack_sum(a2);
        float go = unpack_sum(a3);
#pragma unroll
        for (int m = 4; m <= 16; m <<= 1) {
            gi += __shfl_xor_sync(0xFFFFFFFFu, gi, m);
            gf += __shfl_xor_sync(0xFFFFFFFFu, gf, m);
            gg += __shfl_xor_sync(0xFFFFFFFFu, gg, m);
            go += __shfl_xor_sync(0xFFFFFFFFu, go, m);
        }

        if (wr_lane) {
            float iv = fsigmoid(gxv.x + gi);
            float fv = fsigmoid(gxv.y + gf);
            float gv = ftanh   (gxv.z + gg);
            float ov = fsigmoid(gxv.w + go);
            c = fv * c + iv * gv;
            float h = ov * ftanh(c);

            const int woff = (s & 1) * 136 + (int)rank * 68 + u;
            hbuf[woff] = h;                            // local copy
            asm volatile(
                "mbarrier.arrive.release.cta.shared::cta.b64 _, [%0];"
                :: "r"(bl_a) : "memory");
            asm volatile("st.shared::cluster.f32 [%0], %1;"
                         :: "r"(peer_hbuf + (uint32_t)(woff * 4)), "f"(h)
                         : "memory");
            asm volatile(
                "mbarrier.arrive.release.cluster.shared::cluster.b64 _, [%0];"
                :: "r"(peer_brem) : "memory");
            hcat[(size_t)t * (2 * HID) + dir * HID + gu] = h;
        }
    }

    asm volatile("barrier.cluster.arrive.aligned;" ::: "memory");
    asm volatile("barrier.cluster.wait.aligned;" ::: "memory");
}

// ---------------- kernel 3: layer-1 input projection GEMM --------------------
__global__ void __launch_bounds__(512)
k_gx1(const float* __restrict__ h0,
      const float* __restrict__ Wf, const float* __restrict__ bfi,
      const float* __restrict__ bfh,
      const float* __restrict__ Wb, const float* __restrict__ bbi,
      const float* __restrict__ bbh,
      float* __restrict__ gxf, float* __restrict__ gxb) {
    const int dir = blockIdx.y;
    const float* W  = dir ? Wb  : Wf;
    const float* bi = dir ? bbi : bfi;
    const float* bh = dir ? bbh : bfh;
    float* gx       = dir ? gxb : gxf;

    __shared__ float hs[32 * 256];
    const int t0 = blockIdx.x * 32;
    const int r  = threadIdx.x;                        // gate*128 + unit

    for (int idx = r; idx < 32 * 256; idx += 512)
        hs[idx] = h0[(size_t)t0 * 256 + idx];
    __syncthreads();

    float acc[32];
    const float bias = bi[r] + bh[r];
#pragma unroll
    for (int tt = 0; tt < 32; tt++) acc[tt] = bias;

    const float4* wrow = (const float4*)(W + (size_t)r * 256);
    for (int k4 = 0; k4 < 64; k4++) {
        float4 w4 = wrow[k4];
#pragma unroll
        for (int tt = 0; tt < 32; tt++) {
            float4 hv = *(const float4*)(hs + tt * 256 + k4 * 4);
            acc[tt] += w4.x * hv.x + w4.y * hv.y + w4.z * hv.z + w4.w * hv.w;
        }
    }
    const unsigned dst_r = (r & 127u) * 4u + (r >> 7); // [unit][gate]
#pragma unroll
    for (int tt = 0; tt < 32; tt++)
        gx[(size_t)(t0 + tt) * G4 + dst_r] = acc[tt];
}

// ---------------- kernel 4: FC head ------------------------------------------
__global__ void __launch_bounds__(128)
k_head(const float* __restrict__ h1,
       const float* __restrict__ fc1w, const float* __restrict__ fc1b,
       const float* __restrict__ fc2w, const float* __restrict__ fc2b,
       float* __restrict__ out) {
    __shared__ float hs[8 * 256];
    __shared__ float z[8 * 128];
    const int t0 = blockIdx.x * 8;
    const int j  = threadIdx.x;

    for (int idx = j; idx < 8 * 256; idx += 128)
        hs[idx] = h1[(size_t)t0 * 256 + idx];
    __syncthreads();

    float acc[8];
    const float b = fc1b[j];
#pragma unroll
    for (int tt = 0; tt < 8; tt++) acc[tt] = b;

    const float4* wrow = (const float4*)(fc1w + (size_t)j * 256);
    for (int k4 = 0; k4 < 64; k4++) {
        float4 w4 = wrow[k4];
#pragma unroll
        for (int tt = 0; tt < 8; tt++) {
            float4 hv = *(const float4*)(hs + tt * 256 + k4 * 4);
            acc[tt] += w4.x * hv.x + w4.y * hv.y + w4.z * hv.z + w4.w * hv.w;
        }
    }
#pragma unroll
    for (int tt = 0; tt < 8; tt++) {
        float a = acc[tt];
        z[tt * 128 + j] = a > 0.f ? a : 0.01f * a;
    }
    __syncthreads();

    const int wid  = j >> 5;
    const int lane = j & 31;
#pragma unroll
    for (int q = 0; q < 2; q++) {
        int tt = wid * 2 + q;
        const float* zz = z + tt * 128;
        float s = fc2w[lane]      * zz[lane]
                + fc2w[lane + 32] * zz[lane + 32]
                + fc2w[lane + 64] * zz[lane + 64]
                + fc2w[lane + 96] * zz[lane + 96];
#pragma unroll
        for (int off = 16; off > 0; off >>= 1)
            s += __shfl_down_sync(0xFFFFFFFFu, s, off);
        if (lane == 0)
            out[t0 + tt] = s + fc2b[0];
    }
}

// ---------------- launcher ---------------------------------------------------
extern "C" void kernel_launch(void* const* d_in, const int* in_sizes, int n_in,
                              void* d_out, int out_size) {
    const float* x        = (const float*)d_in[0];
    const float* w_ih_l0  = (const float*)d_in[1];
    const float* w_hh_l0  = (const float*)d_in[2];
    const float* b_ih_l0  = (const float*)d_in[3];
    const float* b_hh_l0  = (const float*)d_in[4];
    const float* w_ih_l0r = (const float*)d_in[5];
    const float* w_hh_l0r = (const float*)d_in[6];
    const float* b_ih_l0r = (const float*)d_in[7];
    const float* b_hh_l0r = (const float*)d_in[8];
    const float* w_ih_l1  = (const float*)d_in[9];
    const float* w_hh_l1  = (const float*)d_in[10];
    const float* b_ih_l1  = (const float*)d_in[11];
    const float* b_hh_l1  = (const float*)d_in[12];
    const float* w_ih_l1r = (const float*)d_in[13];
    const float* w_hh_l1r = (const float*)d_in[14];
    const float* b_ih_l1r = (const float*)d_in[15];
    const float* b_hh_l1r = (const float*)d_in[16];
    const float* fc1_w    = (const float*)d_in[17];
    const float* fc1_b    = (const float*)d_in[18];
    const float* fc2_w    = (const float*)d_in[19];
    const float* fc2_b    = (const float*)d_in[20];
    float* out = (float*)d_out;

    float *gx_base, *h0, *h1;
    cudaGetSymbolAddress((void**)&gx_base, g_gx);
    cudaGetSymbolAddress((void**)&h0, g_h0);
    cudaGetSymbolAddress((void**)&h1, g_h1);
    float* gx0f = gx_base;
    float* gx0b = gx_base + (size_t)1 * T_LEN * G4;
    float* gx1f = gx_base + (size_t)2 * T_LEN * G4;
    float* gx1b = gx_base + (size_t)3 * T_LEN * G4;

    k_gx0<<<(T_LEN * G4 + 255) / 256, 256>>>(x, w_ih_l0, b_ih_l0, b_hh_l0,
                                             w_ih_l0r, b_ih_l0r, b_hh_l0r,
                                             gx0f, gx0b);
    k_lstm2<<<4, 512>>>(gx0f, gx0b, w_hh_l0, w_hh_l0r, h0);
    k_gx1<<<dim3(T_LEN / 32, 2), 512>>>(h0, w_ih_l1, b_ih_l1, b_hh_l1,
                                        w_ih_l1r, b_ih_l1r, b_hh_l1r,
                                        gx1f, gx1b);
    k_lstm2<<<4, 512>>>(gx1f, gx1b, w_hh_l1, w_hh_l1r, h1);
    k_head<<<T_LEN / 8, 128>>>(h1, fc1_w, fc1_b, fc2_w, fc2_b, out);
}